// round 13
// baseline (speedup 1.0000x reference)
#include <cuda_runtime.h>
#include <cstdint>

#define KA 13                 // k-stride (8 + 5 pad) -> <=2-way LDS/STS
#define AWS 420               // 32*KA + 4  (group panel stride, A)
#define BWS 836               // 64*KA + 4  (group panel stride, B)
#define ABUF (4*AWS)          // 1680 floats per A buffer (4 groups)
#define BBUF (4*BWS)          // 3344 floats per B buffer
#define OSM_ROW 321           // 64*5 + 1 (epilogue transpose row stride)
#define SMEM_FLOATS 10272     // max(2*(ABUF+BBUF)=10048, 32*321=10272)
#define SMEM_BYTES (SMEM_FLOATS*4)

#define CSTEP 16384           // +1 channel (floats)

__device__ __forceinline__ uint32_t f2tf32(float f) {
    uint32_t u; asm("cvt.rna.tf32.f32 %0, %1;" : "=r"(u) : "f"(f)); return u;
}
__device__ __forceinline__ void mma_tf32(float& d0, float& d1, float& d2, float& d3,
                                         uint32_t a0, uint32_t a1, uint32_t a2, uint32_t a3,
                                         uint32_t b0, uint32_t b1) {
    asm("mma.sync.aligned.m16n8k8.row.col.f32.tf32.tf32.f32 "
        "{%0,%1,%2,%3},{%4,%5,%6,%7},{%8,%9},{%0,%1,%2,%3};"
        : "+f"(d0), "+f"(d1), "+f"(d2), "+f"(d3)
        : "r"(a0), "r"(a1), "r"(a2), "r"(a3), "r"(b0), "r"(b1));
}

__global__ __launch_bounds__(256, 2)
void lc2d_kernel(const float* __restrict__ x,
                 const float* __restrict__ w,
                 const float* __restrict__ bias,
                 float* __restrict__ out) {
    extern __shared__ float sm[];
    float* AS = sm;                 // [2][group4][b32][KA]
    float* BS = sm + 2 * ABUF;      // [2][group4][f64][KA]

    const int tid  = threadIdx.x;
    const int or_  = blockIdx.y;
    const int oct0 = blockIdx.x * 4;      // 4 pooled cols per CTA
    const int h0   = or_ * 2;
    const int w0   = oct0 * 2;

    // ---- loader mapping (256 threads) ----
    // x: 256 float4 chunks/stage: (xcc2, xrow2, xb32, xj2) -> 1 per thread
    const int xj   = tid & 1;
    const int xb   = (tid >> 1) & 31;
    const int xrow = (tid >> 6) & 1;
    const int xcc  = (tid >> 7) & 1;
    const float* xp = x + ((xb * 32 + xcc) * 128 + h0 + xrow) * 128 + w0 + 4 * xj;

    int a_off[4];
#pragma unroll
    for (int e = 0; e < 4; ++e)
        a_off[e] = (2 * xj + (e >> 1)) * AWS + xb * KA
                 + xcc * 4 + xrow * 2 + (e & 1);

    // w: 512 chunks/stage: (cc2, wrow2, wf64, wj2) -> 2 per thread (cc loop)
    const int wj   = tid & 1;
    const int wf   = (tid >> 1) & 63;
    const int wrow = (tid >> 7) & 1;
    const float* wp = w + ((wf * 32) * 128 + h0 + wrow) * 128 + w0 + 4 * wj;

    int b_off[2][4];
#pragma unroll
    for (int cc = 0; cc < 2; ++cc)
#pragma unroll
        for (int e = 0; e < 4; ++e)
            b_off[cc][e] = (2 * wj + (e >> 1)) * BWS + wf * KA
                         + cc * 4 + wrow * 2 + (e & 1);

    // ---- mma mapping: warp -> (group gp, f-half nh) ----
    const int lane = tid & 31, wid = tid >> 5;
    const int gp = wid >> 1, nh = wid & 1;
    const int g = lane >> 2, t = lane & 3;

    int a_ld[2][4];
#pragma unroll
    for (int mt = 0; mt < 2; ++mt) {
        a_ld[mt][0] = gp * AWS + (mt * 16 + g)     * KA + t;
        a_ld[mt][1] = gp * AWS + (mt * 16 + g + 8) * KA + t;
        a_ld[mt][2] = a_ld[mt][0] + 4;
        a_ld[mt][3] = a_ld[mt][1] + 4;
    }

    float acc[2][4][4];
#pragma unroll
    for (int mt = 0; mt < 2; ++mt)
#pragma unroll
        for (int nt = 0; nt < 4; ++nt)
#pragma unroll
            for (int r = 0; r < 4; ++r) acc[mt][nt][r] = 0.f;

    // ---- two independent prefetch register sets ----
    float4 xr2[2], wr2[2][2];

    auto do_ldg = [&](int set, int stage) {
        const int off = stage * 2 * CSTEP;
        xr2[set] = *(const float4*)(xp + off);
#pragma unroll
        for (int cc = 0; cc < 2; ++cc)
            wr2[set][cc] = *(const float4*)(wp + off + cc * CSTEP);
    };
    auto do_sts = [&](int set, int buf) {
        float* An = AS + buf * ABUF;
        float* Bn = BS + buf * BBUF;
        const float xv[4] = {xr2[set].x, xr2[set].y, xr2[set].z, xr2[set].w};
#pragma unroll
        for (int e = 0; e < 4; ++e)
            An[a_off[e]] = __uint_as_float(f2tf32(xv[e]));
#pragma unroll
        for (int cc = 0; cc < 2; ++cc) {
            const float4 v = wr2[set][cc];
            const float wv[4] = {v.x, v.y, v.z, v.w};
#pragma unroll
            for (int e = 0; e < 4; ++e)
                Bn[b_off[cc][e]] = __uint_as_float(f2tf32(wv[e]));
        }
    };

    // ---- prologue ----
    do_ldg(0, 0);
    do_sts(0, 0);          // stage 0 -> buf 0
    do_ldg(0, 1);          // set0 <- stage 1 (STS'd at s=0)
    do_ldg(1, 2);          // set1 <- stage 2 (STS'd at s=1)
    __syncthreads();

    // ---- main loop: LDG -> STS distance = 2 full stages ----
    for (int s = 0; s < 16; ++s) {
        const int p = s & 1;

        if (s + 1 < 16) do_sts(p, (s + 1) & 1);  // set p holds stage s+1 (loaded s-2)
        if (s + 3 < 16) do_ldg(p, s + 3);        // refill set p for stage s+3

        const float* Ap = AS + (s & 1) * ABUF;
        const float* Bp = BS + (s & 1) * BBUF + gp * BWS + nh * 32 * KA;

        uint32_t a[2][4];
#pragma unroll
        for (int mt = 0; mt < 2; ++mt)
#pragma unroll
            for (int r = 0; r < 4; ++r)
                a[mt][r] = __float_as_uint(Ap[a_ld[mt][r]]);

#pragma unroll
        for (int nt = 0; nt < 4; ++nt) {
            const uint32_t b0 = __float_as_uint(Bp[(nt * 8 + g) * KA + t]);
            const uint32_t b1 = __float_as_uint(Bp[(nt * 8 + g) * KA + t + 4]);
            mma_tf32(acc[0][nt][0], acc[0][nt][1], acc[0][nt][2], acc[0][nt][3],
                     a[0][0], a[0][1], a[0][2], a[0][3], b0, b1);
            mma_tf32(acc[1][nt][0], acc[1][nt][1], acc[1][nt][2], acc[1][nt][3],
                     a[1][0], a[1][1], a[1][2], a[1][3], b0, b1);
        }

        __syncthreads();
    }

    // ---- epilogue: transpose through smem, bias + relu, float4 STG ----
    float* OS = sm;   // safe: last stage ended with __syncthreads()
#pragma unroll
    for (int mt = 0; mt < 2; ++mt)
#pragma unroll
        for (int nt = 0; nt < 4; ++nt) {
            const int r0 = mt * 16 + g;
            const int c0 = nh * 32 + nt * 8 + 2 * t;
            OS[r0 * OSM_ROW + c0 * 5 + gp]             = acc[mt][nt][0];
            OS[r0 * OSM_ROW + (c0 + 1) * 5 + gp]       = acc[mt][nt][1];
            OS[(r0 + 8) * OSM_ROW + c0 * 5 + gp]       = acc[mt][nt][2];
            OS[(r0 + 8) * OSM_ROW + (c0 + 1) * 5 + gp] = acc[mt][nt][3];
        }
    __syncthreads();

    const float* bb = bias + or_ * 64 + oct0;   // + f*4096
    float* ob       = out + or_ * 64 + oct0;    // + (b*64+f)*4096
#pragma unroll
    for (int i = 0; i < 8; ++i) {
        const int p  = tid + 256 * i;
        const int b_ = p >> 6;
        const int f_ = p & 63;
        const float4 bv = *(const float4*)(bb + f_ * 4096);
        const float* row = OS + b_ * OSM_ROW + f_ * 5;
        float4 o;
        o.x = fmaxf(row[0] + bv.x, 0.f);
        o.y = fmaxf(row[1] + bv.y, 0.f);
        o.z = fmaxf(row[2] + bv.z, 0.f);
        o.w = fmaxf(row[3] + bv.w, 0.f);
        *(float4*)(ob + (size_t)(b_ * 64 + f_) * 4096) = o;
    }
}

extern "C" void kernel_launch(void* const* d_in, const int* in_sizes, int n_in,
                              void* d_out, int out_size) {
    const float* x    = (const float*)d_in[0];
    const float* w    = (const float*)d_in[1];
    const float* bias = (const float*)d_in[2];
    float* out        = (float*)d_out;

    cudaFuncSetAttribute(lc2d_kernel,
                         cudaFuncAttributeMaxDynamicSharedMemorySize, SMEM_BYTES);

    dim3 grid(16, 64, 1);
    lc2d_kernel<<<grid, 256, SMEM_BYTES>>>(x, w, bias, out);
}

// round 14
// speedup vs baseline: 1.2030x; 1.2030x over previous
#include <cuda_runtime.h>
#include <cstdint>

#define KA 12                 // k-stride (8 + 4 pad) -> conflict-free fragment LDS
#define AWS 388               // 32*KA + 4  (warp panel stride, A)
#define BWS 772               // 64*KA + 4  (warp panel stride, B)
#define ABUF (8*AWS)          // 3104 floats per A buffer
#define BBUF (8*BWS)          // 6176 floats per B buffer
#define NBUF 3
#define OSM_ROW 581           // 64*9 + 5 (epilogue transpose row stride)
#define SMEM_FLOATS (NBUF*(ABUF+BBUF))   // 27840
#define SMEM_BYTES (SMEM_FLOATS*4)       // 111360 B -> 2 CTAs = 222720 <= 227KB

#define PSTEP (16*32*16384)   // +16 in b/f dimension (floats)
#define CSTEP (2*16384)       // +1 stage = +2 channels (floats)

__device__ __forceinline__ uint32_t f2tf32(float f) {
    uint32_t u; asm("cvt.rna.tf32.f32 %0, %1;" : "=r"(u) : "f"(f)); return u;
}
__device__ __forceinline__ void mma_tf32(float& d0, float& d1, float& d2, float& d3,
                                         uint32_t a0, uint32_t a1, uint32_t a2, uint32_t a3,
                                         uint32_t b0, uint32_t b1) {
    asm("mma.sync.aligned.m16n8k8.row.col.f32.tf32.tf32.f32 "
        "{%0,%1,%2,%3},{%4,%5,%6,%7},{%8,%9},{%0,%1,%2,%3};"
        : "+f"(d0), "+f"(d1), "+f"(d2), "+f"(d3)
        : "r"(a0), "r"(a1), "r"(a2), "r"(a3), "r"(b0), "r"(b1));
}

__global__ __launch_bounds__(256, 2)
void lc2d_kernel(const float* __restrict__ x,
                 const float* __restrict__ w,
                 const float* __restrict__ bias,
                 float* __restrict__ out) {
    extern __shared__ float sm[];
    float* AS = sm;                    // [3][warp8][b32][KA]
    float* BS = sm + NBUF * ABUF;      // [3][warp8][f64][KA]

    const int tid  = threadIdx.x;
    const int or_  = blockIdx.y;
    const int oct0 = blockIdx.x * 8;
    const int h0   = or_ * 2;
    const int w0   = oct0 * 2;

    // ---- loader mapping: tid -> (colq, row, c_local, b-or-f) ----
    const int colq = tid & 3;            // float4 index along 16 input cols
    const int lrow = (tid >> 2) & 1;     // input row within pooled row
    const int lcl  = (tid >> 3) & 1;     // channel within stage
    const int lb   = tid >> 4;           // 0..15 : b (for x) / f (for W)

    const float* xp = x + ((lb * 32 + lcl) * 128 + h0 + lrow) * 128 + w0 + 4 * colq;
    const float* wp = w + ((lb * 32 + lcl) * 128 + h0 + lrow) * 128 + w0 + 4 * colq;

    // STS offsets: col = 4*colq + e ; wp_e = col>>1 ; cp = col&1 ; k = lcl*4+lrow*2+cp
    int a_off[2][4], b_off[4][4];
#pragma unroll
    for (int e = 0; e < 4; ++e) {
        const int wpe = 2 * colq + (e >> 1);
        const int k   = lcl * 4 + lrow * 2 + (e & 1);
#pragma unroll
        for (int i = 0; i < 2; ++i)
            a_off[i][e] = wpe * AWS + (lb + 16 * i) * KA + k;
#pragma unroll
        for (int i = 0; i < 4; ++i)
            b_off[i][e] = wpe * BWS + (lb + 16 * i) * KA + k;
    }

    // ---- mma mapping ----
    const int lane = tid & 31, wid = tid >> 5;
    const int g = lane >> 2, t = lane & 3;

    int a_ld[2][4];
#pragma unroll
    for (int mt = 0; mt < 2; ++mt) {
        a_ld[mt][0] = wid * AWS + (mt * 16 + g)     * KA + t;
        a_ld[mt][1] = wid * AWS + (mt * 16 + g + 8) * KA + t;
        a_ld[mt][2] = a_ld[mt][0] + 4;
        a_ld[mt][3] = a_ld[mt][1] + 4;
    }

    float acc[2][8][4];
#pragma unroll
    for (int mt = 0; mt < 2; ++mt)
#pragma unroll
        for (int nt = 0; nt < 8; ++nt)
#pragma unroll
            for (int r = 0; r < 4; ++r) acc[mt][nt][r] = 0.f;

    float4 xr[2], wr[4];

    // ---- staging helpers ----
    auto do_ldg = [&](int stage) {
        const int off = stage * CSTEP;
#pragma unroll
        for (int i = 0; i < 2; ++i)
            xr[i] = __ldcs((const float4*)(xp + off + i * PSTEP));
#pragma unroll
        for (int i = 0; i < 4; ++i)
            wr[i] = __ldcs((const float4*)(wp + off + i * PSTEP));
    };
    auto do_sts = [&](int buf) {
        float* An = AS + buf * ABUF;
        float* Bn = BS + buf * BBUF;
#pragma unroll
        for (int i = 0; i < 2; ++i) {
            const float v[4] = {xr[i].x, xr[i].y, xr[i].z, xr[i].w};
#pragma unroll
            for (int e = 0; e < 4; ++e)
                An[a_off[i][e]] = __uint_as_float(f2tf32(v[e]));
        }
#pragma unroll
        for (int i = 0; i < 4; ++i) {
            const float v[4] = {wr[i].x, wr[i].y, wr[i].z, wr[i].w};
#pragma unroll
            for (int e = 0; e < 4; ++e)
                Bn[b_off[i][e]] = __uint_as_float(f2tf32(v[e]));
        }
    };

    // ---- prologue: stage0 -> buf0 ; preload stage1 into regs ----
    do_ldg(0);
    do_sts(0);
    do_ldg(1);
    __syncthreads();

    // ---- main loop: split-barrier pipeline over 3 buffers ----
    // stage s: sync(arrivals of stage s-1 STS); STS stage s+1 -> buf (s+1)%3;
    //          arrive; LDG stage s+2; compute buf s%3.
    int cbuf = 0;
    for (int s = 0; s < 16; ++s) {
        if (s > 0) {
            const int bsy = 1 + ((s - 1) & 1);
            asm volatile("bar.sync %0, 512;" :: "r"(bsy));
        }

        int wbuf = cbuf + 1; if (wbuf >= NBUF) wbuf -= NBUF;
        if (s + 1 < 16) do_sts(wbuf);

        {
            const int bar = 1 + (s & 1);
            asm volatile("bar.arrive %0, 512;" :: "r"(bar));
        }

        if (s + 2 < 16) do_ldg(s + 2);

        const float* Ap = AS + cbuf * ABUF;
        const float* Bp = BS + cbuf * BBUF + wid * BWS;

        uint32_t a[2][4];
#pragma unroll
        for (int mt = 0; mt < 2; ++mt)
#pragma unroll
            for (int r = 0; r < 4; ++r)
                a[mt][r] = __float_as_uint(Ap[a_ld[mt][r]]);

#pragma unroll
        for (int nt = 0; nt < 8; ++nt) {
            const uint32_t b0 = __float_as_uint(Bp[(nt * 8 + g) * KA + t]);
            const uint32_t b1 = __float_as_uint(Bp[(nt * 8 + g) * KA + t + 4]);
            mma_tf32(acc[0][nt][0], acc[0][nt][1], acc[0][nt][2], acc[0][nt][3],
                     a[0][0], a[0][1], a[0][2], a[0][3], b0, b1);
            mma_tf32(acc[1][nt][0], acc[1][nt][1], acc[1][nt][2], acc[1][nt][3],
                     a[1][0], a[1][1], a[1][2], a[1][3], b0, b1);
        }

        if (++cbuf >= NBUF) cbuf -= NBUF;
    }
    __syncthreads();   // all compute done before smem reuse

    // ---- epilogue: transpose through smem, bias + relu, coalesced STG ----
    float* OS = sm;
#pragma unroll
    for (int mt = 0; mt < 2; ++mt)
#pragma unroll
        for (int nt = 0; nt < 8; ++nt) {
            const int r0 = mt * 16 + g;
            const int c0 = nt * 8 + 2 * t;
            OS[r0 * OSM_ROW + c0 * 9 + wid]             = acc[mt][nt][0];
            OS[r0 * OSM_ROW + (c0 + 1) * 9 + wid]       = acc[mt][nt][1];
            OS[(r0 + 8) * OSM_ROW + c0 * 9 + wid]       = acc[mt][nt][2];
            OS[(r0 + 8) * OSM_ROW + (c0 + 1) * 9 + wid] = acc[mt][nt][3];
        }
    __syncthreads();

    const float* bb = bias + or_ * 64 + oct0;   // + f*4096
    float* ob       = out + or_ * 64 + oct0;    // + (b*64+f)*4096
#pragma unroll
    for (int i = 0; i < 8; ++i) {
        const int p  = tid + 256 * i;
        const int b_ = p >> 6;
        const int f_ = p & 63;
        const float4 bv0 = *(const float4*)(bb + f_ * 4096);
        const float4 bv1 = *(const float4*)(bb + f_ * 4096 + 4);
        const float* row = OS + b_ * OSM_ROW + f_ * 9;
        float4 o0, o1;
        o0.x = fmaxf(row[0] + bv0.x, 0.f);
        o0.y = fmaxf(row[1] + bv0.y, 0.f);
        o0.z = fmaxf(row[2] + bv0.z, 0.f);
        o0.w = fmaxf(row[3] + bv0.w, 0.f);
        o1.x = fmaxf(row[4] + bv1.x, 0.f);
        o1.y = fmaxf(row[5] + bv1.y, 0.f);
        o1.z = fmaxf(row[6] + bv1.z, 0.f);
        o1.w = fmaxf(row[7] + bv1.w, 0.f);
        float4* dst = (float4*)(ob + (size_t)(b_ * 64 + f_) * 4096);
        dst[0] = o0;
        dst[1] = o1;
    }
}

extern "C" void kernel_launch(void* const* d_in, const int* in_sizes, int n_in,
                              void* d_out, int out_size) {
    const float* x    = (const float*)d_in[0];
    const float* w    = (const float*)d_in[1];
    const float* bias = (const float*)d_in[2];
    float* out        = (float*)d_out;

    cudaFuncSetAttribute(lc2d_kernel,
                         cudaFuncAttributeMaxDynamicSharedMemorySize, SMEM_BYTES);

    dim3 grid(8, 64, 1);
    lc2d_kernel<<<grid, 256, SMEM_BYTES>>>(x, w, bias, out);
}